// round 16
// baseline (speedup 1.0000x reference)
#include <cuda_runtime.h>
#include <math.h>

// ---------------- problem constants ----------------
#define PP    1024
#define MD    512
#define NBF   129
#define KTF   8
#define JD    1032
#define NP    1088
#define NSTEP 17

#define SZ_ETA  528384ll
#define SZ_L1   2113536ll
#define SZ_GEST 1048576ll
#define SZ_B    67633152ll
#define SZ_F    4194304ll
#define SZ_PSI  8192ll
#define SZ_TOT  75526144ll
#define OF_ETA  0ll
#define OF_L1   528384ll
#define OF_GEST 2641920ll
#define OF_B    3690496ll
#define OF_F    71323648ll
#define OF_PSI  75517952ll

// scratch layout (float2 units, relative to outf + OF_B*st)
#define SC_G    0ll
#define SC_Y    1183744ll
#define SC_Y2   1740800ll
#define SC_Y3   2297856ll
#define SC_R    2854912ll
#define SC_P2   3903488ll
#define SC_ID   3969024ll
#define SC_TH   4038656ll
#define SC_L1   4170752ll
#define SC_ETA  6284288ll
#define SC_PSI  6812672ll
#define SC_DV   6816768ll
#define SCCAP   33816576ll

static inline unsigned cdiv(long long a, unsigned b) { return (unsigned)((a + b - 1) / b); }

// ---------------- setup kernels (unchanged from passing R15) ----------------

__global__ void psi_kernel(const float* __restrict__ tf, float* __restrict__ psi) {
    int p = blockIdx.x * 256 + threadIdx.x;
    if (p >= PP) return;
    float x = (p + 0.5f) * 0.25f - 0.5f;
    x = fminf(fmaxf(x, 0.0f), 255.0f);
    int x0 = (int)floorf(x);
    int x1 = min(x0 + 1, 255);
    float w = x - (float)x0;
    #pragma unroll
    for (int k = 0; k < KTF; k++)
        psi[k * PP + p] = tf[k * 256 + x0] * (1.0f - w) + tf[k * 256 + x1] * w;
}

__global__ void theta_kernel(const float* __restrict__ theta,
                             const float* __restrict__ psi,
                             float2* __restrict__ L1c, float2* __restrict__ TH) {
    int p = blockIdx.x;
    if (p >= PP) return;
    float th = theta[p];
    float ps[KTF];
    #pragma unroll
    for (int k = 0; k < KTF; k++) ps[k] = psi[k * PP + p];
    for (int n = threadIdx.x; n < NBF; n += blockDim.x) {
        float fn = (float)(n - 64);
        float s, c;   sincosf(fn * th, &s, &c);
        float s2, c2; sincosf(fn * (th - 3.14159274101257324f), &s2, &c2);
        TH[(long long)n * PP + p] = make_float2(c, s);
        long long r0 = (long long)p * JD + n * KTF;
        long long r1 = (long long)(p + PP) * JD + n * KTF;
        #pragma unroll
        for (int k = 0; k < KTF; k++) {
            L1c[r0 + k] = make_float2(c  * ps[k], s  * ps[k]);
            L1c[r1 + k] = make_float2(c2 * ps[k], s2 * ps[k]);
        }
    }
}

__global__ void initG_kernel(float2* __restrict__ G) {
    long long idx = (long long)blockIdx.x * 256 + threadIdx.x;
    if (idx >= (long long)NP * NP) return;
    long long i = idx / NP, j = idx % NP;
    if (i >= JD || j >= JD)
        G[idx] = make_float2((i == j) ? 1.0f : 0.0f, 0.0f);
}

__global__ void padrows_kernel(float2* __restrict__ Y) {
    long long idx = (long long)blockIdx.x * 256 + threadIdx.x;
    if (idx < (long long)(NP - JD) * MD)
        Y[(long long)JD * MD + idx] = make_float2(0.0f, 0.0f);
}

__global__ void dvec_kernel(const float2* __restrict__ G, float* __restrict__ dv) {
    int i = blockIdx.x * 256 + threadIdx.x;
    if (i < NP)
        dv[i] = (i < JD) ? rsqrtf(fmaxf(G[(long long)i * NP + i].x, 1e-30f)) : 1.0f;
}

__global__ void scaleG_kernel(float2* __restrict__ G, const float* __restrict__ dv) {
    long long idx = (long long)blockIdx.x * 256 + threadIdx.x;
    if (idx >= (long long)NP * NP) return;
    int i = (int)(idx / NP), j = (int)(idx % NP);
    float sc = dv[i] * dv[j];
    float2 v = G[idx];
    G[idx] = make_float2(v.x * sc, v.y * sc);
}

__global__ void scaleY_kernel(float2* __restrict__ Y, const float* __restrict__ dv) {
    long long idx = (long long)blockIdx.x * 256 + threadIdx.x;
    if (idx >= (long long)JD * MD) return;
    float sc = dv[(int)(idx / MD)];
    float2 v = Y[idx];
    Y[idx] = make_float2(v.x * sc, v.y * sc);
}

__global__ void etabuild_kernel(const float2* __restrict__ Y, const float* __restrict__ dv,
                                float2* __restrict__ ec, int add) {
    long long idx = (long long)blockIdx.x * 256 + threadIdx.x;
    if (idx >= (long long)JD * MD) return;
    float sc = dv[(int)(idx / MD)];
    float2 v = Y[idx];
    float2 o = add ? ec[idx] : make_float2(0.f, 0.f);
    o.x += v.x * sc; o.y += v.y * sc;
    ec[idx] = o;
}

__global__ void rinit_kernel(const float* __restrict__ g, float2* __restrict__ R) {
    long long idx = (long long)blockIdx.x * 256 + threadIdx.x;
    if (idx >= (long long)2 * PP * MD) return;
    long long p = idx / MD, m = idx % MD;
    R[idx] = make_float2(g[m * 2 * PP + p], 0.0f);
}

__global__ void copyblk_kernel(float2* __restrict__ dst, long long dld,
                               const float2* __restrict__ src, long long sld,
                               int rows, int cols) {
    long long idx = (long long)blockIdx.x * 256 + threadIdx.x;
    if (idx >= (long long)rows * cols) return;
    long long r = idx / cols, c = idx % cols;
    dst[r * dld + c] = src[r * sld + c];
}

__global__ void realize_kernel(const float2* __restrict__ src, long long n,
                               float* __restrict__ dstf, int st, long long capf) {
    long long e = (long long)blockIdx.x * 256 + threadIdx.x;
    if (e >= n) return;
    long long fo = e * st;
    if (fo + st - 1 >= capf) return;
    float2 v = src[e];
    dstf[fo] = v.x;
    if (st == 2) dstf[fo + 1] = v.y;
}

__global__ void psiout_kernel(const float* __restrict__ ps, float* __restrict__ dstf,
                              int st, long long capf) {
    long long e = (long long)blockIdx.x * 256 + threadIdx.x;
    if (e >= SZ_PSI) return;
    long long fo = e * st;
    if (fo + st - 1 >= capf) return;
    dstf[fo] = ps[e];
    if (st == 2) dstf[fo + 1] = 0.0f;
}

__global__ void marker_kernel(float* __restrict__ o) { if (threadIdx.x == 0) o[0] = 0.0f; }

// ---------------- register-blocked 64x64x16 complex GEMM ----------------
// C[i,j] (epi)= sum_k opA(i,k) * opB(k,j)
// TA=0: A[i*lda+k]; TA=1: A[k*lda+i].  TB=0: B[k*ldb+j]; TB=1: B[j*ldb+k].
// CA/CB conjugate; BREAL: B is real float.
// EPI: 0 store complex; 1 C -= acc; 2 parity-Gram store; 3 float-strided store (st).
#define BMT 64
#define BNT 64
#define BKT 16

template<int TA, bool CA, int TB, bool CB, bool BREAL, int EPI>
__global__ void __launch_bounds__(256)
cgemm(const float2* __restrict__ A, long long lda,
      const void* __restrict__ Bv, long long ldb,
      void* __restrict__ Cv, long long ldc, long long ccap, int st,
      int Md, int Nd, int Kd)
{
    __shared__ float2 As[BKT][BMT + 2];
    __shared__ float2 Bs[BKT][BNT + 2];
    const float2* Bc = (const float2*)Bv;
    const float*  Br = (const float*)Bv;
    int i0 = blockIdx.y * BMT;
    int j0 = blockIdx.x * BNT;
    int t  = threadIdx.x;
    int tr = (t / 16) * 4;
    int tc = (t % 16) * 4;
    float2 acc[4][4];
    #pragma unroll
    for (int a = 0; a < 4; a++)
        #pragma unroll
        for (int b = 0; b < 4; b++) acc[a][b] = make_float2(0.f, 0.f);

    int ktiles = (Kd + BKT - 1) / BKT;
    for (int kt = 0; kt < ktiles; kt++) {
        int k0 = kt * BKT;
        #pragma unroll
        for (int u = 0; u < 4; u++) {
            int idx = t + u * 256;
            int m, k;
            if (TA == 0) { k = idx % BKT; m = idx / BKT; }
            else         { m = idx % BMT; k = idx / BMT; }
            int gm = i0 + m, gk = k0 + k;
            float2 v = make_float2(0.f, 0.f);
            if (gm < Md && gk < Kd)
                v = (TA == 0) ? A[(long long)gm * lda + gk] : A[(long long)gk * lda + gm];
            if (CA) v.y = -v.y;
            As[k][m] = v;
        }
        #pragma unroll
        for (int u = 0; u < 4; u++) {
            int idx = t + u * 256;
            int n, k;
            if (TB == 0) { n = idx % BNT; k = idx / BNT; }
            else         { k = idx % BKT; n = idx / BKT; }
            int gn = j0 + n, gk = k0 + k;
            float2 v = make_float2(0.f, 0.f);
            if (gn < Nd && gk < Kd) {
                long long ib = (TB == 0) ? (long long)gk * ldb + gn : (long long)gn * ldb + gk;
                if (BREAL) {
                    v.x = Br[ib];
                } else {
                    v = Bc[ib];
                    if (CB) v.y = -v.y;
                }
            }
            Bs[k][n] = v;
        }
        __syncthreads();
        #pragma unroll
        for (int kk = 0; kk < BKT; kk++) {
            float2 a[4], b[4];
            #pragma unroll
            for (int x = 0; x < 4; x++) a[x] = As[kk][tr + x];
            #pragma unroll
            for (int x = 0; x < 4; x++) b[x] = Bs[kk][tc + x];
            #pragma unroll
            for (int x = 0; x < 4; x++)
                #pragma unroll
                for (int y = 0; y < 4; y++) {
                    acc[x][y].x = fmaf(a[x].x,  b[y].x, acc[x][y].x);
                    acc[x][y].x = fmaf(-a[x].y, b[y].y, acc[x][y].x);
                    acc[x][y].y = fmaf(a[x].x,  b[y].y, acc[x][y].y);
                    acc[x][y].y = fmaf(a[x].y,  b[y].x, acc[x][y].y);
                }
        }
        __syncthreads();
    }
    #pragma unroll
    for (int x = 0; x < 4; x++) {
        int gi = i0 + tr + x;
        if (gi >= Md) continue;
        #pragma unroll
        for (int y = 0; y < 4; y++) {
            int gj = j0 + tc + y;
            if (gj >= Nd) continue;
            long long off = (long long)gi * ldc + gj;
            if (EPI == 3) {
                long long fo = off * st;
                if (fo + st - 1 >= ccap) continue;
                float* Cf = (float*)Cv;
                Cf[fo] = acc[x][y].x;
                if (st == 2) Cf[fo + 1] = acc[x][y].y;
            } else {
                if (off >= ccap) continue;
                float2* C = (float2*)Cv;
                if (EPI == 0) {
                    C[off] = acc[x][y];
                } else if (EPI == 1) {
                    float2 c = C[off];
                    c.x -= acc[x][y].x; c.y -= acc[x][y].y;
                    C[off] = c;
                } else {
                    int par = ((gi >> 3) ^ (gj >> 3)) & 1;
                    float s = par ? 0.0f : 2.0f;
                    C[off] = make_float2(acc[x][y].x * s, acc[x][y].y * s);
                }
            }
        }
    }
}

// ---------------- Cholesky diagonal pieces (unchanged) ----------------

__global__ void potrf_kernel(float2* __restrict__ Gd) {
    __shared__ float2 Ab[64][65];
    int t = threadIdx.x;
    for (int k = 0; k < 64; k++) Ab[t][k] = Gd[(long long)t * NP + k];
    __syncthreads();
    for (int k = 0; k < 64; k++) {
        if (t == k) Ab[k][k] = make_float2(sqrtf(fmaxf(Ab[k][k].x, 1e-30f)), 0.0f);
        __syncthreads();
        if (t > k) {
            float inv = 1.0f / Ab[k][k].x;
            Ab[t][k].x *= inv; Ab[t][k].y *= inv;
        }
        __syncthreads();
        if (t > k) {
            float2 lrk = Ab[t][k];
            for (int j = k + 1; j <= t; j++) {
                float2 ljk = Ab[j][k];
                Ab[t][j].x -= lrk.x * ljk.x + lrk.y * ljk.y;
                Ab[t][j].y -= lrk.y * ljk.x - lrk.x * ljk.y;
            }
        }
        __syncthreads();
    }
    for (int k = 0; k < 64; k++)
        Gd[(long long)t * NP + k] = (k <= t) ? Ab[t][k] : make_float2(0.0f, 0.0f);
}

__global__ void invert_kernel(const float2* __restrict__ L, float2* __restrict__ iD) {
    __shared__ float2 X[64][64];
    int c = threadIdx.x;
    for (int r = 0; r < 64; r++) {
        if (r < c) { X[r][c] = make_float2(0.f, 0.f); continue; }
        float2 sum = make_float2((r == c) ? 1.0f : 0.0f, 0.0f);
        for (int k = c; k < r; k++) {
            float2 l = L[(long long)r * NP + k];
            float2 x = X[k][c];
            sum.x -= l.x * x.x - l.y * x.y;
            sum.y -= l.x * x.y + l.y * x.x;
        }
        float dd = L[(long long)r * NP + r].x;
        float inv = 1.0f / (dd != 0.0f ? dd : 1e-30f);
        X[r][c] = make_float2(sum.x * inv, sum.y * inv);
    }
    __syncthreads();
    for (int r = 0; r < 64; r++) iD[r * 64 + c] = X[r][c];
}

// ---------------- b and f_pol (unchanged) ----------------

__global__ void b_kernel(const float* __restrict__ etaf, int est,
                         const float* __restrict__ tf,
                         float* __restrict__ outBf, int st, long long capf) {
    __shared__ float2 e8[KTF];
    int n = blockIdx.x, m = blockIdx.y;
    int t = threadIdx.x;
    if (t < KTF) {
        long long e = (long long)(n * KTF + t) * MD + m;
        float re = etaf[e * est];
        float im = (est == 2) ? etaf[e * est + 1] : 0.0f;
        e8[t] = make_float2(re, im);
    }
    __syncthreads();
    float2 ev[KTF];
    #pragma unroll
    for (int k = 0; k < KTF; k++) ev[k] = e8[k];
    #pragma unroll
    for (int u = 0; u < 4; u++) {
        int p = t + u * 256;
        float x = (p + 0.5f) * 0.25f - 0.5f;
        x = fminf(fmaxf(x, 0.0f), 255.0f);
        int x0 = (int)floorf(x);
        int x1 = min(x0 + 1, 255);
        float w = x - (float)x0;
        float2 acc = make_float2(0.f, 0.f);
        #pragma unroll
        for (int k = 0; k < KTF; k++) {
            float ps = tf[k * 256 + x0] * (1.0f - w) + tf[k * 256 + x1] * w;
            acc.x = fmaf(ev[k].x, ps, acc.x);
            acc.y = fmaf(ev[k].y, ps, acc.y);
        }
        long long e = ((long long)m * NBF + n) * PP + p;
        long long fo = e * st;
        if (fo + st - 1 < capf) {
            outBf[fo] = acc.x;
            if (st == 2) outBf[fo + 1] = acc.y;
        }
    }
}

__global__ void fpol_kernel(const float2* __restrict__ ec, const float* __restrict__ psi,
                            const float2* __restrict__ TH,
                            float* __restrict__ outFf, int st, long long capf) {
    __shared__ float2 bs[NBF][8];
    int m = blockIdx.x;
    int t = threadIdx.x;
    int p = blockIdx.y * 256 + t;
    for (int idx = t; idx < NBF * 8; idx += 256) {
        int n = idx >> 3, i = idx & 7;
        float2 acc = make_float2(0.f, 0.f);
        #pragma unroll
        for (int k = 0; k < KTF; k++) {
            float2 e = ec[(long long)(n * KTF + k) * MD + m];
            float ps = psi[k * PP + i * 128];
            acc.x = fmaf(e.x, ps, acc.x);
            acc.y = fmaf(e.y, ps, acc.y);
        }
        bs[n][i] = acc;
    }
    __syncthreads();
    float2 acc[8];
    #pragma unroll
    for (int i = 0; i < 8; i++) acc[i] = make_float2(0.f, 0.f);
    for (int n = 0; n < NBF; n++) {
        float2 th = TH[(long long)n * PP + p];
        #pragma unroll
        for (int i = 0; i < 8; i++) {
            float2 b = bs[n][i];
            acc[i].x += th.x * b.x - th.y * b.y;
            acc[i].y += th.x * b.y + th.y * b.x;
        }
    }
    #pragma unroll
    for (int i = 0; i < 8; i++) {
        long long e = ((long long)m * PP + p) * 8 + i;
        long long fo = e * st;
        if (fo + st - 1 < capf) {
            outFf[fo] = acc[i].x;
            if (st == 2) outFf[fo + 1] = acc[i].y;
        }
    }
}

// ---------------- host ----------------

static void solve_chain(float2* G, float2* iDb, float2* Yb, float2* Y2) {
    for (int s = 0; s < NSTEP; s++) {                     // forward: L z = Y
        float2* iD = iDb + (long long)s * 4096;
        float2* Ys = Yb + (long long)s * 64 * MD;
        cgemm<0, false, 0, false, false, 0><<<dim3(8, 1), 256>>>(
            iD, 64, Ys, MD, Y2, MD, (long long)64 * MD, 1, 64, MD, 64);
        copyblk_kernel<<<cdiv(64ll * MD, 256), 256>>>(Ys, MD, Y2, MD, 64, MD);
        int rem = NP - (s + 1) * 64;
        if (rem > 0)
            cgemm<0, false, 0, false, false, 1><<<dim3(8, cdiv(rem, 64)), 256>>>(
                G + (long long)(s + 1) * 64 * NP + (long long)s * 64, NP,
                Ys, MD,
                Yb + (long long)(s + 1) * 64 * MD, MD, (long long)rem * MD, 1,
                rem, MD, 64);
    }
    for (int s = NSTEP - 1; s >= 0; s--) {                // backward: L^H x = z
        float2* iD = iDb + (long long)s * 4096;
        float2* Ys = Yb + (long long)s * 64 * MD;
        int rem = NP - (s + 1) * 64;
        if (rem > 0)
            cgemm<1, true, 0, false, false, 1><<<dim3(8, 1), 256>>>(
                G + (long long)(s + 1) * 64 * NP + (long long)s * 64, NP,
                Yb + (long long)(s + 1) * 64 * MD, MD,
                Ys, MD, (long long)64 * MD, 1, 64, MD, rem);
        cgemm<1, true, 0, false, false, 0><<<dim3(8, 1), 256>>>(
            iD, 64, Ys, MD, Y2, MD, (long long)64 * MD, 1, 64, MD, 64);
        copyblk_kernel<<<cdiv(64ll * MD, 256), 256>>>(Ys, MD, Y2, MD, 64, MD);
    }
}

extern "C" void kernel_launch(void* const* d_in, const int* in_sizes, int n_in,
                              void* d_out, int out_size) {
    const float *g = 0, *tf = 0, *th = 0;
    for (int i = 0; i < n_in; i++) {
        if      (in_sizes[i] == MD * 2 * PP) g  = (const float*)d_in[i];
        else if (in_sizes[i] == KTF * 256)   tf = (const float*)d_in[i];
        else if (in_sizes[i] == PP)          th = (const float*)d_in[i];
    }
    if (!g || !tf || !th || !d_out || out_size <= 0) return;
    long long oc = (long long)out_size;
    float* outf = (float*)d_out;

    if (oc < SZ_TOT) { marker_kernel<<<1, 32>>>(outf); return; }
    int st = (oc >= 2ll * SZ_TOT) ? 2 : 1;
    long long capf = oc;

    float2* SB  = (float2*)(outf + OF_B * st);
    float2* G   = SB + SC_G;
    float2* Yb  = SB + SC_Y;
    float2* Y2  = SB + SC_Y2;
    float2* Y3  = SB + SC_Y3;
    float2* R   = SB + SC_R;
    float2* P2  = SB + SC_P2;
    float2* iDb = SB + SC_ID;
    float2* TH  = SB + SC_TH;
    float2* L1c = SB + SC_L1;
    float2* ec  = SB + SC_ETA;
    float*  PS  = (float*)(SB + SC_PSI);
    float*  DV  = (float*)(SB + SC_DV);

    // setup
    psi_kernel<<<4, 256>>>(tf, PS);
    theta_kernel<<<PP, 128>>>(th, PS, L1c, TH);
    initG_kernel<<<cdiv((long long)NP * NP, 256), 256>>>(G);
    padrows_kernel<<<cdiv((long long)(NP - JD) * MD, 256), 256>>>(Yb);

    // Gram (top half + parity), equilibrate
    cgemm<1, true, 0, false, false, 2><<<dim3(17, 17), 256>>>(
        L1c, JD, L1c, JD, G, NP, SCCAP - SC_G, 1, JD, JD, PP);
    dvec_kernel<<<cdiv(NP, 256), 256>>>(G, DV);
    scaleG_kernel<<<cdiv((long long)NP * NP, 256), 256>>>(G, DV);

    // RHS = L1^H g^T
    cgemm<1, true, 1, false, true, 0><<<dim3(8, 17), 256>>>(
        L1c, JD, g, 2 * PP, Yb, MD, SCCAP - SC_Y, 1, JD, MD, 2 * PP);
    scaleY_kernel<<<cdiv((long long)JD * MD, 256), 256>>>(Yb, DV);

    // blocked Cholesky, nb = 64
    for (int s = 0; s < NSTEP; s++) {
        float2* Gd = G + (long long)s * 64 * NP + (long long)s * 64;
        float2* iD = iDb + (long long)s * 4096;
        potrf_kernel<<<1, 64>>>(Gd);
        invert_kernel<<<1, 64>>>(Gd, iD);
        int rem = NP - (s + 1) * 64;
        if (rem > 0) {
            float2* pan = G + (long long)(s + 1) * 64 * NP + (long long)s * 64;
            cgemm<0, false, 1, true, false, 0><<<dim3(1, cdiv(rem, 64)), 256>>>(
                pan, NP, iD, 64, P2, 64, SCCAP - SC_P2, 1, rem, 64, 64);
            copyblk_kernel<<<cdiv((long long)rem * 64, 256), 256>>>(pan, NP, P2, 64, rem, 64);
            cgemm<0, false, 1, true, false, 1><<<dim3(cdiv(rem, 64), cdiv(rem, 64)), 256>>>(
                pan, NP, pan, NP,
                G + (long long)(s + 1) * 64 * NP + (long long)(s + 1) * 64, NP,
                (long long)rem * NP, 1, rem, rem, 64);
        }
    }

    // solve + eta_hat
    solve_chain(G, iDb, Yb, Y2);
    etabuild_kernel<<<cdiv((long long)JD * MD, 256), 256>>>(Yb, DV, ec, 0);

    // one Björck refinement step vs the true LS residual
    rinit_kernel<<<cdiv((long long)2 * PP * MD, 256), 256>>>(g, R);
    cgemm<0, false, 0, false, false, 1><<<dim3(8, 32), 256>>>(
        L1c, JD, ec, MD, R, MD, SCCAP - SC_R, 1, 2 * PP, MD, JD);
    cgemm<1, true, 0, false, false, 0><<<dim3(8, 17), 256>>>(
        L1c, JD, R, MD, Y3, MD, SCCAP - SC_Y3, 1, JD, MD, 2 * PP);
    padrows_kernel<<<cdiv((long long)(NP - JD) * MD, 256), 256>>>(Y3);
    scaleY_kernel<<<cdiv((long long)JD * MD, 256), 256>>>(Y3, DV);
    solve_chain(G, iDb, Y3, Y2);
    etabuild_kernel<<<cdiv((long long)JD * MD, 256), 256>>>(Y3, DV, ec, 1);

    // outputs
    realize_kernel<<<cdiv(SZ_ETA, 256), 256>>>(ec, SZ_ETA, outf + OF_ETA * st, st, capf - OF_ETA * st);
    realize_kernel<<<cdiv(SZ_L1, 256), 256>>>(L1c, SZ_L1, outf + OF_L1 * st, st, capf - OF_L1 * st);
    psiout_kernel<<<cdiv(SZ_PSI, 256), 256>>>(PS, outf + OF_PSI * st, st, capf - OF_PSI * st);
    // g_est^T(m,p) = sum_j eta[j,m] * L1[p,j]   (float-strided store)
    cgemm<1, false, 1, false, false, 3><<<dim3(32, 8), 256>>>(
        ec, MD, L1c, JD, outf + OF_GEST * st, 2 * PP, capf - OF_GEST * st, st, MD, 2 * PP, JD);
    // f_pol (reads scratch) before b (overwrites scratch)
    fpol_kernel<<<dim3(MD, PP / 256), 256>>>(ec, PS, TH, outf + OF_F * st, st, capf - OF_F * st);
    b_kernel<<<dim3(NBF, MD), 256>>>(outf + OF_ETA * st, st, tf,
                                     outf + OF_B * st, st, capf - OF_B * st);
}

// round 17
// speedup vs baseline: 1.3557x; 1.3557x over previous
#include <cuda_runtime.h>
#include <math.h>

// ---------------- problem constants ----------------
#define PP    1024
#define MD    512
#define NBF   129
#define KTF   8
#define JD    1032
#define NP    1088
#define NSTEP 17

#define SZ_ETA  528384ll
#define SZ_L1   2113536ll
#define SZ_GEST 1048576ll
#define SZ_B    67633152ll
#define SZ_F    4194304ll
#define SZ_PSI  8192ll
#define SZ_TOT  75526144ll
#define OF_ETA  0ll
#define OF_L1   528384ll
#define OF_GEST 2641920ll
#define OF_B    3690496ll
#define OF_F    71323648ll
#define OF_PSI  75517952ll

// scratch layout (float2 units, relative to outf + OF_B*st)
#define SC_G    0ll
#define SC_Y    1183744ll                        // NP*NP
#define SC_Y2   (SC_Y  + (long long)NP * MD)     // 1740800
#define SC_Y3   (SC_Y2 + (long long)NP * MD)     // 2297856
#define SC_R    (SC_Y3 + (long long)NP * MD)     // 2854912
#define SC_ID   (SC_R  + (long long)2 * PP * MD) // 3903488
#define SC_TH   (SC_ID + (long long)NSTEP * 4096)
#define SC_L1   (SC_TH + (long long)NBF * PP)
#define SC_ETA  (SC_L1 + (long long)2 * PP * JD)
#define SC_PSI  (SC_ETA + (long long)JD * MD)    // 8192 floats
#define SC_DV   (SC_PSI + 4096ll)                // 1088 floats
#define SC_W    (SC_DV + 1024ll)                 // NP*NP
#define SC_T    (SC_W + (long long)NP * NP)      // 64*NP
#define SC_END  (SC_T + (long long)64 * NP)      // ~9.3M << 33.8M cap
#define SCCAP   33816576ll

static inline unsigned cdiv(long long a, unsigned b) { return (unsigned)((a + b - 1) / b); }

// ---------------- setup kernels ----------------

__global__ void psi_kernel(const float* __restrict__ tf, float* __restrict__ psi) {
    int p = blockIdx.x * 256 + threadIdx.x;
    if (p >= PP) return;
    float x = (p + 0.5f) * 0.25f - 0.5f;
    x = fminf(fmaxf(x, 0.0f), 255.0f);
    int x0 = (int)floorf(x);
    int x1 = min(x0 + 1, 255);
    float w = x - (float)x0;
    #pragma unroll
    for (int k = 0; k < KTF; k++)
        psi[k * PP + p] = tf[k * 256 + x0] * (1.0f - w) + tf[k * 256 + x1] * w;
}

__global__ void theta_kernel(const float* __restrict__ theta,
                             const float* __restrict__ psi,
                             float2* __restrict__ L1c, float2* __restrict__ TH) {
    int p = blockIdx.x;
    if (p >= PP) return;
    float th = theta[p];
    float ps[KTF];
    #pragma unroll
    for (int k = 0; k < KTF; k++) ps[k] = psi[k * PP + p];
    for (int n = threadIdx.x; n < NBF; n += blockDim.x) {
        float fn = (float)(n - 64);
        float s, c;   sincosf(fn * th, &s, &c);
        float s2, c2; sincosf(fn * (th - 3.14159274101257324f), &s2, &c2);
        TH[(long long)n * PP + p] = make_float2(c, s);
        long long r0 = (long long)p * JD + n * KTF;
        long long r1 = (long long)(p + PP) * JD + n * KTF;
        #pragma unroll
        for (int k = 0; k < KTF; k++) {
            L1c[r0 + k] = make_float2(c  * ps[k], s  * ps[k]);
            L1c[r1 + k] = make_float2(c2 * ps[k], s2 * ps[k]);
        }
    }
}

__global__ void initG_kernel(float2* __restrict__ G) {
    long long idx = (long long)blockIdx.x * 256 + threadIdx.x;
    if (idx >= (long long)NP * NP) return;
    long long i = idx / NP, j = idx % NP;
    if (i >= JD || j >= JD)
        G[idx] = make_float2((i == j) ? 1.0f : 0.0f, 0.0f);
}

__global__ void initW_kernel(float2* __restrict__ W) {
    long long idx = (long long)blockIdx.x * 256 + threadIdx.x;
    if (idx < (long long)NP * NP) W[idx] = make_float2(0.0f, 0.0f);
}

__global__ void padrows_kernel(float2* __restrict__ Y) {
    long long idx = (long long)blockIdx.x * 256 + threadIdx.x;
    if (idx < (long long)(NP - JD) * MD)
        Y[(long long)JD * MD + idx] = make_float2(0.0f, 0.0f);
}

__global__ void dvec_kernel(const float2* __restrict__ G, float* __restrict__ dv) {
    int i = blockIdx.x * 256 + threadIdx.x;
    if (i < NP)
        dv[i] = (i < JD) ? rsqrtf(fmaxf(G[(long long)i * NP + i].x, 1e-30f)) : 1.0f;
}

__global__ void scaleG_kernel(float2* __restrict__ G, const float* __restrict__ dv) {
    long long idx = (long long)blockIdx.x * 256 + threadIdx.x;
    if (idx >= (long long)NP * NP) return;
    int i = (int)(idx / NP), j = (int)(idx % NP);
    float sc = dv[i] * dv[j];
    float2 v = G[idx];
    G[idx] = make_float2(v.x * sc, v.y * sc);
}

__global__ void scaleY_kernel(float2* __restrict__ Y, const float* __restrict__ dv) {
    long long idx = (long long)blockIdx.x * 256 + threadIdx.x;
    if (idx >= (long long)JD * MD) return;
    float sc = dv[(int)(idx / MD)];
    float2 v = Y[idx];
    Y[idx] = make_float2(v.x * sc, v.y * sc);
}

__global__ void etabuild_kernel(const float2* __restrict__ Y, const float* __restrict__ dv,
                                float2* __restrict__ ec, int add) {
    long long idx = (long long)blockIdx.x * 256 + threadIdx.x;
    if (idx >= (long long)JD * MD) return;
    float sc = dv[(int)(idx / MD)];
    float2 v = Y[idx];
    float2 o = add ? ec[idx] : make_float2(0.f, 0.f);
    o.x += v.x * sc; o.y += v.y * sc;
    ec[idx] = o;
}

__global__ void rinit_kernel(const float* __restrict__ g, float2* __restrict__ R) {
    long long idx = (long long)blockIdx.x * 256 + threadIdx.x;
    if (idx >= (long long)2 * PP * MD) return;
    long long p = idx / MD, m = idx % MD;
    R[idx] = make_float2(g[m * 2 * PP + p], 0.0f);
}

__global__ void realize_kernel(const float2* __restrict__ src, long long n,
                               float* __restrict__ dstf, int st, long long capf) {
    long long e = (long long)blockIdx.x * 256 + threadIdx.x;
    if (e >= n) return;
    long long fo = e * st;
    if (fo + st - 1 >= capf) return;
    float2 v = src[e];
    dstf[fo] = v.x;
    if (st == 2) dstf[fo + 1] = v.y;
}

__global__ void psiout_kernel(const float* __restrict__ ps, float* __restrict__ dstf,
                              int st, long long capf) {
    long long e = (long long)blockIdx.x * 256 + threadIdx.x;
    if (e >= SZ_PSI) return;
    long long fo = e * st;
    if (fo + st - 1 >= capf) return;
    dstf[fo] = ps[e];
    if (st == 2) dstf[fo + 1] = 0.0f;
}

__global__ void marker_kernel(float* __restrict__ o) { if (threadIdx.x == 0) o[0] = 0.0f; }

// ---------------- register-blocked 64x64x16 complex GEMM ----------------
// C[i,j] (epi)= sum_k opA(i,k) * opB(k,j)
// TA=0: A[i*lda+k]; TA=1: A[k*lda+i].  TB=0: B[k*ldb+j]; TB=1: B[j*ldb+k].
// EPI: 0 store; 1 C -= acc; 2 parity-Gram store; 3 float-strided store; 4 store -acc.
#define BMT 64
#define BNT 64
#define BKT 16

template<int TA, bool CA, int TB, bool CB, bool BREAL, int EPI>
__global__ void __launch_bounds__(256)
cgemm(const float2* __restrict__ A, long long lda,
      const void* __restrict__ Bv, long long ldb,
      void* __restrict__ Cv, long long ldc, long long ccap, int st,
      int Md, int Nd, int Kd)
{
    __shared__ float2 As[BKT][BMT + 2];
    __shared__ float2 Bs[BKT][BNT + 2];
    const float2* Bc = (const float2*)Bv;
    const float*  Br = (const float*)Bv;
    int i0 = blockIdx.y * BMT;
    int j0 = blockIdx.x * BNT;
    int t  = threadIdx.x;
    int tr = (t / 16) * 4;
    int tc = (t % 16) * 4;
    float2 acc[4][4];
    #pragma unroll
    for (int a = 0; a < 4; a++)
        #pragma unroll
        for (int b = 0; b < 4; b++) acc[a][b] = make_float2(0.f, 0.f);

    int ktiles = (Kd + BKT - 1) / BKT;
    for (int kt = 0; kt < ktiles; kt++) {
        int k0 = kt * BKT;
        #pragma unroll
        for (int u = 0; u < 4; u++) {
            int idx = t + u * 256;
            int m, k;
            if (TA == 0) { k = idx % BKT; m = idx / BKT; }
            else         { m = idx % BMT; k = idx / BMT; }
            int gm = i0 + m, gk = k0 + k;
            float2 v = make_float2(0.f, 0.f);
            if (gm < Md && gk < Kd)
                v = (TA == 0) ? A[(long long)gm * lda + gk] : A[(long long)gk * lda + gm];
            if (CA) v.y = -v.y;
            As[k][m] = v;
        }
        #pragma unroll
        for (int u = 0; u < 4; u++) {
            int idx = t + u * 256;
            int n, k;
            if (TB == 0) { n = idx % BNT; k = idx / BNT; }
            else         { k = idx % BKT; n = idx / BKT; }
            int gn = j0 + n, gk = k0 + k;
            float2 v = make_float2(0.f, 0.f);
            if (gn < Nd && gk < Kd) {
                long long ib = (TB == 0) ? (long long)gk * ldb + gn : (long long)gn * ldb + gk;
                if (BREAL) {
                    v.x = Br[ib];
                } else {
                    v = Bc[ib];
                    if (CB) v.y = -v.y;
                }
            }
            Bs[k][n] = v;
        }
        __syncthreads();
        #pragma unroll
        for (int kk = 0; kk < BKT; kk++) {
            float2 a[4], b[4];
            #pragma unroll
            for (int x = 0; x < 4; x++) a[x] = As[kk][tr + x];
            #pragma unroll
            for (int x = 0; x < 4; x++) b[x] = Bs[kk][tc + x];
            #pragma unroll
            for (int x = 0; x < 4; x++)
                #pragma unroll
                for (int y = 0; y < 4; y++) {
                    acc[x][y].x = fmaf(a[x].x,  b[y].x, acc[x][y].x);
                    acc[x][y].x = fmaf(-a[x].y, b[y].y, acc[x][y].x);
                    acc[x][y].y = fmaf(a[x].x,  b[y].y, acc[x][y].y);
                    acc[x][y].y = fmaf(a[x].y,  b[y].x, acc[x][y].y);
                }
        }
        __syncthreads();
    }
    #pragma unroll
    for (int x = 0; x < 4; x++) {
        int gi = i0 + tr + x;
        if (gi >= Md) continue;
        #pragma unroll
        for (int y = 0; y < 4; y++) {
            int gj = j0 + tc + y;
            if (gj >= Nd) continue;
            long long off = (long long)gi * ldc + gj;
            if (EPI == 3) {
                long long fo = off * st;
                if (fo + st - 1 >= ccap) continue;
                float* Cf = (float*)Cv;
                Cf[fo] = acc[x][y].x;
                if (st == 2) Cf[fo + 1] = acc[x][y].y;
            } else {
                if (off >= ccap) continue;
                float2* C = (float2*)Cv;
                if (EPI == 0) {
                    C[off] = acc[x][y];
                } else if (EPI == 1) {
                    float2 c = C[off];
                    c.x -= acc[x][y].x; c.y -= acc[x][y].y;
                    C[off] = c;
                } else if (EPI == 4) {
                    C[off] = make_float2(-acc[x][y].x, -acc[x][y].y);
                } else {
                    int par = ((gi >> 3) ^ (gj >> 3)) & 1;
                    float s = par ? 0.0f : 2.0f;
                    C[off] = make_float2(acc[x][y].x * s, acc[x][y].y * s);
                }
            }
        }
    }
}

// ---------------- fused Cholesky diag: potrf + triangular inverse ----------------
// 64 threads. Factorizes the 64x64 diag block in shared, writes L back to G,
// then inverts L using the UPPER triangle of the same shared tile (thread =
// column, race-free: lower triangle is read-only, each thread writes only its
// own upper row). Writes inv(L) to iD [64x64, zeros above diag] and into the
// diagonal block of W.
__global__ void potrf_inv_kernel(float2* __restrict__ Gd, float2* __restrict__ iD,
                                 float2* __restrict__ Wd) {
    __shared__ float2 Ab[64][65];
    int t = threadIdx.x;
    for (int k = 0; k < 64; k++) Ab[t][k] = Gd[(long long)t * NP + k];
    __syncthreads();
    for (int k = 0; k < 64; k++) {
        if (t == k) Ab[k][k] = make_float2(sqrtf(fmaxf(Ab[k][k].x, 1e-30f)), 0.0f);
        __syncthreads();
        if (t > k) {
            float inv = 1.0f / Ab[k][k].x;
            Ab[t][k].x *= inv; Ab[t][k].y *= inv;
        }
        __syncthreads();
        if (t > k) {
            float2 lrk = Ab[t][k];
            for (int j = k + 1; j <= t; j++) {
                float2 ljk = Ab[j][k];
                Ab[t][j].x -= lrk.x * ljk.x + lrk.y * ljk.y;
                Ab[t][j].y -= lrk.y * ljk.x - lrk.x * ljk.y;
            }
        }
        __syncthreads();
    }
    // write back L (zeros above diag)
    for (int k = 0; k < 64; k++)
        Gd[(long long)t * NP + k] = (k <= t) ? Ab[t][k] : make_float2(0.0f, 0.0f);
    // invert: thread c computes column c of X = L^{-1}, stores X[r][c] (r>c)
    // transposed into Ab[c][r] (upper). Lower triangle is read-only here.
    int c = t;
    float xcc = 1.0f / Ab[c][c].x;
    for (int r = c + 1; r < 64; r++) {
        float2 l0 = Ab[r][c];
        float2 sum = make_float2(l0.x * xcc, l0.y * xcc);   // k = c term (xcc real)
        for (int k = c + 1; k < r; k++) {
            float2 l = Ab[r][k];
            float2 x = Ab[c][k];                            // X[k][c]
            sum.x += l.x * x.x - l.y * x.y;
            sum.y += l.x * x.y + l.y * x.x;
        }
        float inv = -1.0f / Ab[r][r].x;
        Ab[c][r] = make_float2(sum.x * inv, sum.y * inv);
    }
    for (int r = 0; r < 64; r++) {
        float2 val;
        if (r < c)       val = make_float2(0.0f, 0.0f);
        else if (r == c) val = make_float2(xcc, 0.0f);
        else             val = Ab[c][r];
        iD[r * 64 + c] = val;
        Wd[(long long)r * NP + c] = val;
    }
}

// ---------------- b and f_pol ----------------

__global__ void b_kernel(const float* __restrict__ etaf, int est,
                         const float* __restrict__ tf,
                         float* __restrict__ outBf, int st, long long capf) {
    __shared__ float2 e8[KTF];
    int n = blockIdx.x, m = blockIdx.y;
    int t = threadIdx.x;
    if (t < KTF) {
        long long e = (long long)(n * KTF + t) * MD + m;
        float re = etaf[e * est];
        float im = (est == 2) ? etaf[e * est + 1] : 0.0f;
        e8[t] = make_float2(re, im);
    }
    __syncthreads();
    float2 ev[KTF];
    #pragma unroll
    for (int k = 0; k < KTF; k++) ev[k] = e8[k];
    #pragma unroll
    for (int u = 0; u < 4; u++) {
        int p = t + u * 256;
        float x = (p + 0.5f) * 0.25f - 0.5f;
        x = fminf(fmaxf(x, 0.0f), 255.0f);
        int x0 = (int)floorf(x);
        int x1 = min(x0 + 1, 255);
        float w = x - (float)x0;
        float2 acc = make_float2(0.f, 0.f);
        #pragma unroll
        for (int k = 0; k < KTF; k++) {
            float ps = tf[k * 256 + x0] * (1.0f - w) + tf[k * 256 + x1] * w;
            acc.x = fmaf(ev[k].x, ps, acc.x);
            acc.y = fmaf(ev[k].y, ps, acc.y);
        }
        long long e = ((long long)m * NBF + n) * PP + p;
        long long fo = e * st;
        if (fo + st - 1 < capf) {
            outBf[fo] = acc.x;
            if (st == 2) outBf[fo + 1] = acc.y;
        }
    }
}

__global__ void fpol_kernel(const float2* __restrict__ ec, const float* __restrict__ psi,
                            const float2* __restrict__ TH,
                            float* __restrict__ outFf, int st, long long capf) {
    __shared__ float2 bs[NBF][8];
    int m = blockIdx.x;
    int t = threadIdx.x;
    int p = blockIdx.y * 256 + t;
    for (int idx = t; idx < NBF * 8; idx += 256) {
        int n = idx >> 3, i = idx & 7;
        float2 acc = make_float2(0.f, 0.f);
        #pragma unroll
        for (int k = 0; k < KTF; k++) {
            float2 e = ec[(long long)(n * KTF + k) * MD + m];
            float ps = psi[k * PP + i * 128];
            acc.x = fmaf(e.x, ps, acc.x);
            acc.y = fmaf(e.y, ps, acc.y);
        }
        bs[n][i] = acc;
    }
    __syncthreads();
    float2 acc[8];
    #pragma unroll
    for (int i = 0; i < 8; i++) acc[i] = make_float2(0.f, 0.f);
    for (int n = 0; n < NBF; n++) {
        float2 th = TH[(long long)n * PP + p];
        #pragma unroll
        for (int i = 0; i < 8; i++) {
            float2 b = bs[n][i];
            acc[i].x += th.x * b.x - th.y * b.y;
            acc[i].y += th.x * b.y + th.y * b.x;
        }
    }
    #pragma unroll
    for (int i = 0; i < 8; i++) {
        long long e = ((long long)m * PP + p) * 8 + i;
        long long fo = e * st;
        if (fo + st - 1 < capf) {
            outFf[fo] = acc[i].x;
            if (st == 2) outFf[fo + 1] = acc[i].y;
        }
    }
}

// ---------------- host ----------------

extern "C" void kernel_launch(void* const* d_in, const int* in_sizes, int n_in,
                              void* d_out, int out_size) {
    const float *g = 0, *tf = 0, *th = 0;
    for (int i = 0; i < n_in; i++) {
        if      (in_sizes[i] == MD * 2 * PP) g  = (const float*)d_in[i];
        else if (in_sizes[i] == KTF * 256)   tf = (const float*)d_in[i];
        else if (in_sizes[i] == PP)          th = (const float*)d_in[i];
    }
    if (!g || !tf || !th || !d_out || out_size <= 0) return;
    long long oc = (long long)out_size;
    float* outf = (float*)d_out;

    if (oc < SZ_TOT) { marker_kernel<<<1, 32>>>(outf); return; }
    int st = (oc >= 2ll * SZ_TOT) ? 2 : 1;
    long long capf = oc;

    float2* SB  = (float2*)(outf + OF_B * st);
    float2* G   = SB + SC_G;
    float2* Yb  = SB + SC_Y;
    float2* Y2  = SB + SC_Y2;
    float2* Y3  = SB + SC_Y3;
    float2* R   = SB + SC_R;
    float2* iDb = SB + SC_ID;
    float2* TH  = SB + SC_TH;
    float2* L1c = SB + SC_L1;
    float2* ec  = SB + SC_ETA;
    float*  PS  = (float*)(SB + SC_PSI);
    float*  DV  = (float*)(SB + SC_DV);
    float2* W   = SB + SC_W;
    float2* T   = SB + SC_T;

    // setup
    psi_kernel<<<4, 256>>>(tf, PS);
    theta_kernel<<<PP, 128>>>(th, PS, L1c, TH);
    initG_kernel<<<cdiv((long long)NP * NP, 256), 256>>>(G);
    initW_kernel<<<cdiv((long long)NP * NP, 256), 256>>>(W);
    padrows_kernel<<<cdiv((long long)(NP - JD) * MD, 256), 256>>>(Yb);

    // Gram (top half + parity), equilibrate
    cgemm<1, true, 0, false, false, 2><<<dim3(17, 17), 256>>>(
        L1c, JD, L1c, JD, G, NP, (long long)NP * NP, 1, JD, JD, PP);
    dvec_kernel<<<cdiv(NP, 256), 256>>>(G, DV);
    scaleG_kernel<<<cdiv((long long)NP * NP, 256), 256>>>(G, DV);

    // RHS = L1^H g^T
    cgemm<1, true, 1, false, true, 0><<<dim3(8, 17), 256>>>(
        L1c, JD, g, 2 * PP, Yb, MD, (long long)NP * MD, 1, JD, MD, 2 * PP);
    scaleY_kernel<<<cdiv((long long)JD * MD, 256), 256>>>(Yb, DV);

    // blocked Cholesky, nb = 64: fused potrf+inverse, in-place trsm, update
    for (int s = 0; s < NSTEP; s++) {
        float2* Gd = G + (long long)s * 64 * NP + (long long)s * 64;
        float2* iD = iDb + (long long)s * 4096;
        float2* Wd = W + (long long)s * 64 * NP + (long long)s * 64;
        potrf_inv_kernel<<<1, 64>>>(Gd, iD, Wd);
        int rem = NP - (s + 1) * 64;
        if (rem > 0) {
            float2* pan = G + (long long)(s + 1) * 64 * NP + (long long)s * 64;
            // pan = pan * iD^H   (in place: each block reads only its own region)
            cgemm<0, false, 1, true, false, 0><<<dim3(1, cdiv(rem, 64)), 256>>>(
                pan, NP, iD, 64, pan, NP, (long long)rem * NP, 1, rem, 64, 64);
            // trailing update: G22 -= pan * pan^H
            cgemm<0, false, 1, true, false, 1><<<dim3(cdiv(rem, 64), cdiv(rem, 64)), 256>>>(
                pan, NP, pan, NP,
                G + (long long)(s + 1) * 64 * NP + (long long)(s + 1) * 64, NP,
                (long long)rem * NP, 1, rem, rem, 64);
        }
    }

    // W = inv(L), block row i:  W[i,0:i] = -iD_i * (L[i,0:i] @ W[0:i,0:i])
    for (int i = 1; i < NSTEP; i++) {
        cgemm<0, false, 0, false, false, 0><<<dim3(i, 1), 256>>>(
            G + (long long)i * 64 * NP, NP, W, NP,
            T, NP, (long long)64 * NP, 1, 64, 64 * i, 64 * i);
        cgemm<0, false, 0, false, false, 4><<<dim3(i, 1), 256>>>(
            iDb + (long long)i * 4096, 64, T, NP,
            W + (long long)i * 64 * NP, NP, (long long)64 * NP, 1, 64, 64 * i, 64);
    }

    // solve G x = Y  via  x = W^H (W Y)
    cgemm<0, false, 0, false, false, 0><<<dim3(8, 17), 256>>>(
        W, NP, Yb, MD, Y2, MD, (long long)NP * MD, 1, NP, MD, NP);
    cgemm<1, true, 0, false, false, 0><<<dim3(8, 17), 256>>>(
        W, NP, Y2, MD, Yb, MD, (long long)NP * MD, 1, NP, MD, NP);
    etabuild_kernel<<<cdiv((long long)JD * MD, 256), 256>>>(Yb, DV, ec, 0);

    // one Björck refinement step vs the true LS residual
    rinit_kernel<<<cdiv((long long)2 * PP * MD, 256), 256>>>(g, R);
    cgemm<0, false, 0, false, false, 1><<<dim3(8, 32), 256>>>(
        L1c, JD, ec, MD, R, MD, (long long)2 * PP * MD, 1, 2 * PP, MD, JD);
    cgemm<1, true, 0, false, false, 0><<<dim3(8, 17), 256>>>(
        L1c, JD, R, MD, Y3, MD, (long long)NP * MD, 1, JD, MD, 2 * PP);
    padrows_kernel<<<cdiv((long long)(NP - JD) * MD, 256), 256>>>(Y3);
    scaleY_kernel<<<cdiv((long long)JD * MD, 256), 256>>>(Y3, DV);
    cgemm<0, false, 0, false, false, 0><<<dim3(8, 17), 256>>>(
        W, NP, Y3, MD, Y2, MD, (long long)NP * MD, 1, NP, MD, NP);
    cgemm<1, true, 0, false, false, 0><<<dim3(8, 17), 256>>>(
        W, NP, Y2, MD, Y3, MD, (long long)NP * MD, 1, NP, MD, NP);
    etabuild_kernel<<<cdiv((long long)JD * MD, 256), 256>>>(Y3, DV, ec, 1);

    // outputs
    realize_kernel<<<cdiv(SZ_ETA, 256), 256>>>(ec, SZ_ETA, outf + OF_ETA * st, st, capf - OF_ETA * st);
    realize_kernel<<<cdiv(SZ_L1, 256), 256>>>(L1c, SZ_L1, outf + OF_L1 * st, st, capf - OF_L1 * st);
    psiout_kernel<<<cdiv(SZ_PSI, 256), 256>>>(PS, outf + OF_PSI * st, st, capf - OF_PSI * st);
    cgemm<1, false, 1, false, false, 3><<<dim3(32, 8), 256>>>(
        ec, MD, L1c, JD, outf + OF_GEST * st, 2 * PP, capf - OF_GEST * st, st, MD, 2 * PP, JD);
    fpol_kernel<<<dim3(MD, PP / 256), 256>>>(ec, PS, TH, outf + OF_F * st, st, capf - OF_F * st);
    b_kernel<<<dim3(NBF, MD), 256>>>(outf + OF_ETA * st, st, tf,
                                     outf + OF_B * st, st, capf - OF_B * st);
}